// round 1
// baseline (speedup 1.0000x reference)
#include <cuda_runtime.h>
#include <math.h>
#include <stdint.h>

#define NJ 52
#define NV 6890
#define NB 10
#define NP 459            // (NJ-1)*9
#define BATCH 512
#define R3 20670          // NV*3
#define RP 21504          // padded row count for transposed dirs (21 blocks * 1024)
#define NVP 6912          // padded NV for transposed weights
#define C1_BT 16          // batches per thread in naked GEMM

__constant__ int c_parents[NJ] = {
    -1,0,0,0,1,2,3,4,5,6,7,8,9,9,9,12,13,14,16,17,18,19,20,22,23,20,25,26,
    20,28,29,20,31,32,20,34,35,21,37,38,21,40,41,21,43,44,21,46,47,21,49,50};

// ---- scratch (__device__ globals: allocation-free) ----
__device__ float d_pdT[NP * RP];        // posedirs^T, padded rows   (~39.5 MB)
__device__ float d_sdT[NB * RP];        // shapedirs^T, padded rows
__device__ float d_vtp[RP];             // v_template flat, padded
__device__ float d_wT [NJ * NVP];       // weights^T, padded
__device__ float d_pm [BATCH * NP];     // pose_map
__device__ float d_A2 [BATCH * NJ * 12];// A2 rows 0..2 (3x4 per joint)
__device__ float d_J0 [NJ * 3];
__device__ float d_Jsh[NJ * 3 * NB];

// ---------------------------------------------------------------------------
// generic tiled transpose: in (M x N) row-major -> out (N x ldOut), zero-safe
// ---------------------------------------------------------------------------
__global__ void transpose_kernel(const float* __restrict__ in, float* __restrict__ out,
                                 int M, int N, int ldOut) {
    __shared__ float tile[32][33];
    int c0 = blockIdx.x * 32;
    int r0 = blockIdx.y * 32;
    int tx = threadIdx.x, ty = threadIdx.y;   // block (32,8)
#pragma unroll
    for (int i = 0; i < 32; i += 8) {
        int r = r0 + ty + i, c = c0 + tx;
        tile[ty + i][tx] = (r < M && c < N) ? in[(size_t)r * N + c] : 0.f;
    }
    __syncthreads();
#pragma unroll
    for (int i = 0; i < 32; i += 8) {
        int c = c0 + ty + i, r = r0 + tx;
        if (c < N && r < ldOut)
            out[(size_t)c * ldOut + r] = tile[tx][ty + i];
    }
}

__global__ void copy_vt_kernel(const float* __restrict__ vt) {
    int i = blockIdx.x * 256 + threadIdx.x;
    if (i < R3) d_vtp[i] = vt[i];
}

// ---------------------------------------------------------------------------
// fold J_regressor: J0 = Jreg @ v_template, Jsh = Jreg @ shapedirs
// ---------------------------------------------------------------------------
__global__ void jreg_kernel(const float* __restrict__ Jreg,
                            const float* __restrict__ vt,
                            const float* __restrict__ sd) {
    int j = blockIdx.x;
    int tid = threadIdx.x;          // 256 threads
    float acc[33];
#pragma unroll
    for (int o = 0; o < 33; o++) acc[o] = 0.f;
    for (int v = tid; v < NV; v += 256) {
        float jr = Jreg[(size_t)j * NV + v];
#pragma unroll
        for (int k = 0; k < 3; k++) {
            acc[k] += jr * vt[v * 3 + k];
#pragma unroll
            for (int q = 0; q < NB; q++)
                acc[3 + k * NB + q] += jr * sd[(size_t)(v * 3 + k) * NB + q];
        }
    }
    __shared__ float red[256];
    for (int o = 0; o < 33; o++) {
        red[tid] = acc[o];
        __syncthreads();
        for (int s = 128; s > 0; s >>= 1) {
            if (tid < s) red[tid] += red[tid + s];
            __syncthreads();
        }
        if (tid == 0) {
            if (o < 3) d_J0[j * 3 + o] = red[0];
            else       d_Jsh[j * 30 + (o - 3)] = red[0];
        }
        __syncthreads();
    }
}

// ---------------------------------------------------------------------------
// per-batch: rodrigues, pose_map, th_j, kinematic chain, A2, th_jtr
// ---------------------------------------------------------------------------
__global__ void pose_kernel(const float* __restrict__ pose,
                            const float* __restrict__ betas,
                            const float* __restrict__ trans,
                            float* __restrict__ out_jtr) {
    int b = blockIdx.x;
    int tid = threadIdx.x;          // 64 threads
    __shared__ float rot_s[NJ][9];
    __shared__ float j_s[NJ][3];
    __shared__ float A_s[NJ][12];
    __shared__ float bet_s[NB];

    if (tid < NB) bet_s[tid] = betas[b * NB + tid];
    if (tid < NJ) {
        float x = pose[b * NJ * 3 + tid * 3 + 0];
        float y = pose[b * NJ * 3 + tid * 3 + 1];
        float z = pose[b * NJ * 3 + tid * 3 + 2];
        float th = sqrtf(x * x + y * y + z * z + 1e-8f);
        float inv = 1.f / th;
        float kx = x * inv, ky = y * inv, kz = z * inv;
        float s = sinf(th), c = cosf(th), oc = 1.f - c;
        rot_s[tid][0] = c + oc * kx * kx;
        rot_s[tid][1] = -s * kz + oc * kx * ky;
        rot_s[tid][2] =  s * ky + oc * kx * kz;
        rot_s[tid][3] =  s * kz + oc * ky * kx;
        rot_s[tid][4] = c + oc * ky * ky;
        rot_s[tid][5] = -s * kx + oc * ky * kz;
        rot_s[tid][6] = -s * ky + oc * kz * kx;
        rot_s[tid][7] =  s * kx + oc * kz * ky;
        rot_s[tid][8] = c + oc * kz * kz;
    }
    __syncthreads();

    // th_j = J0 + Jsh @ betas
    for (int idx = tid; idx < NJ * 3; idx += 64) {
        int j = idx / 3, k = idx % 3;
        float v = d_J0[idx];
#pragma unroll
        for (int q = 0; q < NB; q++)
            v += d_Jsh[j * 30 + k * NB + q] * bet_s[q];
        j_s[j][k] = v;
    }
    // pose_map = rot[1:] - I
    for (int idx = tid; idx < NP; idx += 64) {
        int j = idx / 9 + 1, e = idx % 9;
        float iv = (e == 0 || e == 4 || e == 8) ? 1.f : 0.f;
        d_pm[(size_t)b * NP + idx] = rot_s[j][e] - iv;
    }
    __syncthreads();

    if (tid == 0) {
        // root transform
#pragma unroll
        for (int m = 0; m < 3; m++) {
#pragma unroll
            for (int n = 0; n < 3; n++) A_s[0][m * 4 + n] = rot_s[0][m * 3 + n];
            A_s[0][m * 4 + 3] = j_s[0][m];
        }
        for (int i = 1; i < NJ; i++) {
            int p = c_parents[i];
            float t0 = j_s[i][0] - j_s[p][0];
            float t1 = j_s[i][1] - j_s[p][1];
            float t2 = j_s[i][2] - j_s[p][2];
#pragma unroll
            for (int m = 0; m < 3; m++) {
                float r0 = A_s[p][m * 4 + 0], r1 = A_s[p][m * 4 + 1], r2 = A_s[p][m * 4 + 2];
#pragma unroll
                for (int n = 0; n < 3; n++)
                    A_s[i][m * 4 + n] = r0 * rot_s[i][0 * 3 + n] + r1 * rot_s[i][1 * 3 + n] + r2 * rot_s[i][2 * 3 + n];
                A_s[i][m * 4 + 3] = r0 * t0 + r1 * t1 + r2 * t2 + A_s[p][m * 4 + 3];
            }
        }
    }
    __syncthreads();

    // A2 (col3 -= R*th_j) and th_jtr
    for (int idx = tid; idx < NJ * 3; idx += 64) {
        int j = idx / 3, m = idx % 3;
        float r0 = A_s[j][m * 4 + 0], r1 = A_s[j][m * 4 + 1], r2 = A_s[j][m * 4 + 2];
        float t  = A_s[j][m * 4 + 3];
        float tmp = r0 * j_s[j][0] + r1 * j_s[j][1] + r2 * j_s[j][2];
        float* a2 = &d_A2[((size_t)b * NJ + j) * 12 + m * 4];
        a2[0] = r0; a2[1] = r1; a2[2] = r2; a2[3] = t - tmp;
        out_jtr[(size_t)b * NJ * 3 + j * 3 + m] = t + trans[b * 3 + m];
    }
}

// ---------------------------------------------------------------------------
// naked = v_template + shapedirs@betas + posedirs@pose_map   (the big GEMM)
// block: 256 threads, each thread: 4 rows (float4) x 16 batches
// ---------------------------------------------------------------------------
__global__ __launch_bounds__(256, 2) void naked_kernel(const float* __restrict__ betas,
                                                       float* __restrict__ out_vposed,
                                                       float* __restrict__ out_naked) {
    __shared__ float pm_s[NP][C1_BT];     // [459][16]
    __shared__ float bet_s[NB][C1_BT];
    int b0 = blockIdx.y * C1_BT;
    int tid = threadIdx.x;

    for (int idx = tid; idx < NP * C1_BT; idx += 256) {
        int t = idx / NP, p = idx % NP;
        pm_s[p][t] = d_pm[(size_t)(b0 + t) * NP + p];
    }
    for (int idx = tid; idx < NB * C1_BT; idx += 256) {
        int t = idx / NB, q = idx % NB;
        bet_s[q][t] = betas[(b0 + t) * NB + q];
    }
    __syncthreads();

    int r = blockIdx.x * 1024 + tid * 4;   // r < RP always (padded arrays)
    float4 vt = *(const float4*)&d_vtp[r];
    float4 acc[C1_BT];
#pragma unroll
    for (int t = 0; t < C1_BT; t++) acc[t] = vt;

#pragma unroll
    for (int q = 0; q < NB; q++) {
        float4 sd = *(const float4*)&d_sdT[(size_t)q * RP + r];
#pragma unroll
        for (int t = 0; t < C1_BT; t++) {
            float bv = bet_s[q][t];
            acc[t].x += sd.x * bv; acc[t].y += sd.y * bv;
            acc[t].z += sd.z * bv; acc[t].w += sd.w * bv;
        }
    }

#pragma unroll 2
    for (int p = 0; p < NP; p++) {
        float4 pd = *(const float4*)&d_pdT[(size_t)p * RP + r];
#pragma unroll
        for (int t = 0; t < C1_BT; t++) {
            float pv = pm_s[p][t];
            acc[t].x += pd.x * pv; acc[t].y += pd.y * pv;
            acc[t].z += pd.z * pv; acc[t].w += pd.w * pv;
        }
    }

    if (r < R3) {
        bool hi_ok = (r + 2 < R3);   // R3 even, r multiple of 4 -> float2 granularity safe
#pragma unroll
        for (int t = 0; t < C1_BT; t++) {
            size_t base = (size_t)(b0 + t) * R3 + r;
            float2 lo = make_float2(acc[t].x, acc[t].y);
            float2 hi = make_float2(acc[t].z, acc[t].w);
            *(float2*)(out_vposed + base) = lo;
            *(float2*)(out_naked  + base) = lo;
            if (hi_ok) {
                *(float2*)(out_vposed + base + 2) = hi;
                *(float2*)(out_naked  + base + 2) = hi;
            }
        }
    }
}

// ---------------------------------------------------------------------------
// skinning: T = weights @ A2 (fused), verts = T[:, :3]@naked + T[:,3] + trans
// block: 128 threads, thread: 4 vertices, 1 batch (blockIdx.y)
// ---------------------------------------------------------------------------
__global__ __launch_bounds__(128) void skin_kernel(const float* __restrict__ trans,
                                                   const float* __restrict__ naked_in,
                                                   float* __restrict__ out_verts) {
    __shared__ float A2_s[NJ * 12];
    int b = blockIdx.y;
    int tid = threadIdx.x;
    for (int i = tid; i < NJ * 12; i += 128)
        A2_s[i] = d_A2[(size_t)b * NJ * 12 + i];
    __syncthreads();

    int v0 = (blockIdx.x * 128 + tid) * 4;
    if (v0 >= NV) return;

    float T[4][12];
#pragma unroll
    for (int vi = 0; vi < 4; vi++)
#pragma unroll
        for (int e = 0; e < 12; e++) T[vi][e] = 0.f;

    for (int j = 0; j < NJ; j++) {
        float4 w = *(const float4*)&d_wT[(size_t)j * NVP + v0];
        const float4* a2 = (const float4*)&A2_s[j * 12];
        float4 a0 = a2[0], a1 = a2[1], a3 = a2[2];
        float wv[4] = {w.x, w.y, w.z, w.w};
#pragma unroll
        for (int vi = 0; vi < 4; vi++) {
            float ww = wv[vi];
            T[vi][0] += ww * a0.x; T[vi][1] += ww * a0.y; T[vi][2]  += ww * a0.z; T[vi][3]  += ww * a0.w;
            T[vi][4] += ww * a1.x; T[vi][5] += ww * a1.y; T[vi][6]  += ww * a1.z; T[vi][7]  += ww * a1.w;
            T[vi][8] += ww * a3.x; T[vi][9] += ww * a3.y; T[vi][10] += ww * a3.z; T[vi][11] += ww * a3.w;
        }
    }

    float tx = trans[b * 3 + 0], ty = trans[b * 3 + 1], tz = trans[b * 3 + 2];
#pragma unroll
    for (int vi = 0; vi < 4; vi++) {
        int v = v0 + vi;
        if (v >= NV) break;
        size_t nb = (size_t)b * R3 + v * 3;
        float nx = naked_in[nb + 0], ny = naked_in[nb + 1], nz = naked_in[nb + 2];
        out_verts[nb + 0] = T[vi][0] * nx + T[vi][1] * ny + T[vi][2]  * nz + T[vi][3]  + tx;
        out_verts[nb + 1] = T[vi][4] * nx + T[vi][5] * ny + T[vi][6]  * nz + T[vi][7]  + ty;
        out_verts[nb + 2] = T[vi][8] * nx + T[vi][9] * ny + T[vi][10] * nz + T[vi][11] + tz;
    }
}

// ---------------------------------------------------------------------------
extern "C" void kernel_launch(void* const* d_in, const int* in_sizes, int n_in,
                              void* d_out, int out_size) {
    (void)in_sizes; (void)n_in; (void)out_size;
    const float* pose  = (const float*)d_in[0];
    const float* betas = (const float*)d_in[1];
    const float* trans = (const float*)d_in[2];
    const float* vt    = (const float*)d_in[3];
    const float* sd    = (const float*)d_in[4];
    const float* pd    = (const float*)d_in[5];
    const float* Jreg  = (const float*)d_in[6];
    const float* wgt   = (const float*)d_in[7];

    float* out        = (float*)d_out;
    float* out_verts  = out;
    float* out_jtr    = out_verts + (size_t)BATCH * R3;
    float* out_vposed = out_jtr   + (size_t)BATCH * NJ * 3;
    float* out_naked  = out_vposed + (size_t)BATCH * R3;

    void *p_pdT, *p_sdT, *p_wT;
    cudaGetSymbolAddress(&p_pdT, d_pdT);
    cudaGetSymbolAddress(&p_sdT, d_sdT);
    cudaGetSymbolAddress(&p_wT,  d_wT);

    dim3 tb(32, 8);
    // posedirs flat is (R3 x NP) row-major -> transpose to (NP x RP)
    transpose_kernel<<<dim3((NP + 31) / 32, (R3 + 31) / 32), tb>>>(pd, (float*)p_pdT, R3, NP, RP);
    // shapedirs flat is (R3 x NB) -> (NB x RP)
    transpose_kernel<<<dim3((NB + 31) / 32, (R3 + 31) / 32), tb>>>(sd, (float*)p_sdT, R3, NB, RP);
    // weights (NV x NJ) -> (NJ x NVP)
    transpose_kernel<<<dim3((NJ + 31) / 32, (NV + 31) / 32), tb>>>(wgt, (float*)p_wT, NV, NJ, NVP);
    copy_vt_kernel<<<(R3 + 255) / 256, 256>>>(vt);

    jreg_kernel<<<NJ, 256>>>(Jreg, vt, sd);
    pose_kernel<<<BATCH, 64>>>(pose, betas, trans, out_jtr);

    naked_kernel<<<dim3(21, BATCH / C1_BT), 256>>>(betas, out_vposed, out_naked);
    skin_kernel<<<dim3((NV + 511) / 512, BATCH), 128>>>(trans, out_naked, out_verts);
}

// round 2
// speedup vs baseline: 1.0066x; 1.0066x over previous
#include <cuda_runtime.h>
#include <math.h>
#include <stdint.h>

#define NJ 52
#define NV 6890
#define NB 10
#define NP 459            // (NJ-1)*9
#define BATCH 512
#define R3 20670          // NV*3
#define RP 21504          // padded row count for transposed dirs (21 blocks * 1024)
#define NVP 6912          // padded NV for transposed weights
#define C1_BT 16          // batches per block in naked GEMM (8 f32x2 pairs)
#define SK_BT 4           // batches per block in skin

typedef unsigned long long ull;

__constant__ int c_parents[NJ] = {
    -1,0,0,0,1,2,3,4,5,6,7,8,9,9,9,12,13,14,16,17,18,19,20,22,23,20,25,26,
    20,28,29,20,31,32,20,34,35,21,37,38,21,40,41,21,43,44,21,46,47,21,49,50};

// ---- scratch (__device__ globals: allocation-free) ----
__device__ float d_pdT[NP * RP];        // posedirs^T, padded rows   (~39.5 MB)
__device__ float d_sdT[NB * RP];        // shapedirs^T, padded rows
__device__ float d_vtp[RP];             // v_template flat, padded
__device__ float d_wT [NJ * NVP];       // weights^T, padded
__device__ float d_pm [BATCH * NP];     // pose_map
__device__ float d_A2 [BATCH * NJ * 12];// A2 rows 0..2 (3x4 per joint)
__device__ float d_J0 [NJ * 3];
__device__ float d_Jsh[NJ * 3 * NB];

// ---------------- f32x2 packed-math helpers (PTX-only on sm_103a) ----------
__device__ __forceinline__ ull fma2(ull a, ull b, ull c) {
    ull d;
    asm("fma.rn.f32x2 %0, %1, %2, %3;" : "=l"(d) : "l"(a), "l"(b), "l"(c));
    return d;
}
__device__ __forceinline__ ull splat2(float x) {
    ull r;
    asm("mov.b64 %0, {%1, %2};" : "=l"(r) : "f"(x), "f"(x));
    return r;
}
__device__ __forceinline__ float2 unpack2(ull u) {
    float2 f;
    asm("mov.b64 {%0, %1}, %2;" : "=f"(f.x), "=f"(f.y) : "l"(u));
    return f;
}

// ---------------------------------------------------------------------------
// generic tiled transpose: in (M x N) row-major -> out (N x ldOut), zero-safe
// ---------------------------------------------------------------------------
__global__ void transpose_kernel(const float* __restrict__ in, float* __restrict__ out,
                                 int M, int N, int ldOut) {
    __shared__ float tile[32][33];
    int c0 = blockIdx.x * 32;
    int r0 = blockIdx.y * 32;
    int tx = threadIdx.x, ty = threadIdx.y;   // block (32,8)
#pragma unroll
    for (int i = 0; i < 32; i += 8) {
        int r = r0 + ty + i, c = c0 + tx;
        tile[ty + i][tx] = (r < M && c < N) ? in[(size_t)r * N + c] : 0.f;
    }
    __syncthreads();
#pragma unroll
    for (int i = 0; i < 32; i += 8) {
        int c = c0 + ty + i, r = r0 + tx;
        if (c < N && r < ldOut)
            out[(size_t)c * ldOut + r] = tile[tx][ty + i];
    }
}

__global__ void copy_vt_kernel(const float* __restrict__ vt) {
    int i = blockIdx.x * 256 + threadIdx.x;
    if (i < R3) d_vtp[i] = vt[i];
}

// ---------------------------------------------------------------------------
// fold J_regressor: J0 = Jreg @ v_template, Jsh = Jreg @ shapedirs
// ---------------------------------------------------------------------------
__global__ void jreg_kernel(const float* __restrict__ Jreg,
                            const float* __restrict__ vt,
                            const float* __restrict__ sd) {
    int j = blockIdx.x;
    int tid = threadIdx.x;          // 256 threads
    float acc[33];
#pragma unroll
    for (int o = 0; o < 33; o++) acc[o] = 0.f;
    for (int v = tid; v < NV; v += 256) {
        float jr = Jreg[(size_t)j * NV + v];
#pragma unroll
        for (int k = 0; k < 3; k++) {
            acc[k] += jr * vt[v * 3 + k];
#pragma unroll
            for (int q = 0; q < NB; q++)
                acc[3 + k * NB + q] += jr * sd[(size_t)(v * 3 + k) * NB + q];
        }
    }
    __shared__ float red[256];
    for (int o = 0; o < 33; o++) {
        red[tid] = acc[o];
        __syncthreads();
        for (int s = 128; s > 0; s >>= 1) {
            if (tid < s) red[tid] += red[tid + s];
            __syncthreads();
        }
        if (tid == 0) {
            if (o < 3) d_J0[j * 3 + o] = red[0];
            else       d_Jsh[j * 30 + (o - 3)] = red[0];
        }
        __syncthreads();
    }
}

// ---------------------------------------------------------------------------
// per-batch: rodrigues, pose_map, th_j, kinematic chain, A2, th_jtr
// ---------------------------------------------------------------------------
__global__ void pose_kernel(const float* __restrict__ pose,
                            const float* __restrict__ betas,
                            const float* __restrict__ trans,
                            float* __restrict__ out_jtr) {
    int b = blockIdx.x;
    int tid = threadIdx.x;          // 64 threads
    __shared__ float rot_s[NJ][9];
    __shared__ float j_s[NJ][3];
    __shared__ float A_s[NJ][12];
    __shared__ float bet_s[NB];

    if (tid < NB) bet_s[tid] = betas[b * NB + tid];
    if (tid < NJ) {
        float x = pose[b * NJ * 3 + tid * 3 + 0];
        float y = pose[b * NJ * 3 + tid * 3 + 1];
        float z = pose[b * NJ * 3 + tid * 3 + 2];
        float th = sqrtf(x * x + y * y + z * z + 1e-8f);
        float inv = 1.f / th;
        float kx = x * inv, ky = y * inv, kz = z * inv;
        float s = sinf(th), c = cosf(th), oc = 1.f - c;
        rot_s[tid][0] = c + oc * kx * kx;
        rot_s[tid][1] = -s * kz + oc * kx * ky;
        rot_s[tid][2] =  s * ky + oc * kx * kz;
        rot_s[tid][3] =  s * kz + oc * ky * kx;
        rot_s[tid][4] = c + oc * ky * ky;
        rot_s[tid][5] = -s * kx + oc * ky * kz;
        rot_s[tid][6] = -s * ky + oc * kz * kx;
        rot_s[tid][7] =  s * kx + oc * kz * ky;
        rot_s[tid][8] = c + oc * kz * kz;
    }
    __syncthreads();

    // th_j = J0 + Jsh @ betas
    for (int idx = tid; idx < NJ * 3; idx += 64) {
        int j = idx / 3, k = idx % 3;
        float v = d_J0[idx];
#pragma unroll
        for (int q = 0; q < NB; q++)
            v += d_Jsh[j * 30 + k * NB + q] * bet_s[q];
        j_s[j][k] = v;
    }
    // pose_map = rot[1:] - I
    for (int idx = tid; idx < NP; idx += 64) {
        int j = idx / 9 + 1, e = idx % 9;
        float iv = (e == 0 || e == 4 || e == 8) ? 1.f : 0.f;
        d_pm[(size_t)b * NP + idx] = rot_s[j][e] - iv;
    }
    __syncthreads();

    if (tid == 0) {
#pragma unroll
        for (int m = 0; m < 3; m++) {
#pragma unroll
            for (int n = 0; n < 3; n++) A_s[0][m * 4 + n] = rot_s[0][m * 3 + n];
            A_s[0][m * 4 + 3] = j_s[0][m];
        }
        for (int i = 1; i < NJ; i++) {
            int p = c_parents[i];
            float t0 = j_s[i][0] - j_s[p][0];
            float t1 = j_s[i][1] - j_s[p][1];
            float t2 = j_s[i][2] - j_s[p][2];
#pragma unroll
            for (int m = 0; m < 3; m++) {
                float r0 = A_s[p][m * 4 + 0], r1 = A_s[p][m * 4 + 1], r2 = A_s[p][m * 4 + 2];
#pragma unroll
                for (int n = 0; n < 3; n++)
                    A_s[i][m * 4 + n] = r0 * rot_s[i][0 * 3 + n] + r1 * rot_s[i][1 * 3 + n] + r2 * rot_s[i][2 * 3 + n];
                A_s[i][m * 4 + 3] = r0 * t0 + r1 * t1 + r2 * t2 + A_s[p][m * 4 + 3];
            }
        }
    }
    __syncthreads();

    for (int idx = tid; idx < NJ * 3; idx += 64) {
        int j = idx / 3, m = idx % 3;
        float r0 = A_s[j][m * 4 + 0], r1 = A_s[j][m * 4 + 1], r2 = A_s[j][m * 4 + 2];
        float t  = A_s[j][m * 4 + 3];
        float tmp = r0 * j_s[j][0] + r1 * j_s[j][1] + r2 * j_s[j][2];
        float* a2 = &d_A2[((size_t)b * NJ + j) * 12 + m * 4];
        a2[0] = r0; a2[1] = r1; a2[2] = r2; a2[3] = t - tmp;
        out_jtr[(size_t)b * NJ * 3 + j * 3 + m] = t + trans[b * 3 + m];
    }
}

// ---------------------------------------------------------------------------
// naked = v_template + shapedirs@betas + posedirs@pose_map   (the big GEMM)
// f32x2 packed: thread owns 4 rows x 16 batches as acc2[row][batch_pair]
// ---------------------------------------------------------------------------
__global__ __launch_bounds__(256, 2) void naked_kernel(const float* __restrict__ betas,
                                                       float* __restrict__ out_vposed,
                                                       float* __restrict__ out_naked) {
    __shared__ __align__(16) float pm_s[NP][C1_BT];     // [459][16]
    __shared__ __align__(16) float bet_s[NB][C1_BT];
    int b0 = blockIdx.y * C1_BT;
    int tid = threadIdx.x;

    for (int idx = tid; idx < NP * C1_BT; idx += 256) {
        int t = idx / NP, p = idx % NP;
        pm_s[p][t] = d_pm[(size_t)(b0 + t) * NP + p];
    }
    for (int idx = tid; idx < NB * C1_BT; idx += 256) {
        int t = idx / NB, q = idx % NB;
        bet_s[q][t] = betas[(b0 + t) * NB + q];
    }
    __syncthreads();

    int r = blockIdx.x * 1024 + tid * 4;   // r < RP always (padded arrays)
    float4 vt = *(const float4*)&d_vtp[r];

    ull acc2[4][8];   // [row 0..3][batch pair 0..7], lanes = (b even, b odd)
    {
        ull vx = splat2(vt.x), vy = splat2(vt.y), vz = splat2(vt.z), vw = splat2(vt.w);
#pragma unroll
        for (int tp = 0; tp < 8; tp++) {
            acc2[0][tp] = vx; acc2[1][tp] = vy; acc2[2][tp] = vz; acc2[3][tp] = vw;
        }
    }

#pragma unroll
    for (int q = 0; q < NB; q++) {
        float4 sd = *(const float4*)&d_sdT[(size_t)q * RP + r];
        ull sx = splat2(sd.x), sy = splat2(sd.y), sz = splat2(sd.z), sw = splat2(sd.w);
        const ull* brow = (const ull*)&bet_s[q][0];
#pragma unroll
        for (int tp = 0; tp < 8; tp++) {
            ull bv = brow[tp];
            acc2[0][tp] = fma2(sx, bv, acc2[0][tp]);
            acc2[1][tp] = fma2(sy, bv, acc2[1][tp]);
            acc2[2][tp] = fma2(sz, bv, acc2[2][tp]);
            acc2[3][tp] = fma2(sw, bv, acc2[3][tp]);
        }
    }

#pragma unroll 2
    for (int p = 0; p < NP; p++) {
        float4 pd = *(const float4*)&d_pdT[(size_t)p * RP + r];
        ull px = splat2(pd.x), py = splat2(pd.y), pz = splat2(pd.z), pw = splat2(pd.w);
        const ull* prow = (const ull*)&pm_s[p][0];
#pragma unroll
        for (int tp = 0; tp < 8; tp++) {
            ull pv = prow[tp];
            acc2[0][tp] = fma2(px, pv, acc2[0][tp]);
            acc2[1][tp] = fma2(py, pv, acc2[1][tp]);
            acc2[2][tp] = fma2(pz, pv, acc2[2][tp]);
            acc2[3][tp] = fma2(pw, pv, acc2[3][tp]);
        }
    }

    if (r < R3) {
        bool hi_ok = (r + 2 < R3);
#pragma unroll
        for (int tp = 0; tp < 8; tp++) {
            float2 r0 = unpack2(acc2[0][tp]);
            float2 r1 = unpack2(acc2[1][tp]);
            float2 r2 = unpack2(acc2[2][tp]);
            float2 r3 = unpack2(acc2[3][tp]);
#pragma unroll
            for (int lane = 0; lane < 2; lane++) {
                size_t base = (size_t)(b0 + 2 * tp + lane) * R3 + r;
                float2 lo = (lane == 0) ? make_float2(r0.x, r1.x) : make_float2(r0.y, r1.y);
                float2 hi = (lane == 0) ? make_float2(r2.x, r3.x) : make_float2(r2.y, r3.y);
                *(float2*)(out_vposed + base) = lo;
                *(float2*)(out_naked  + base) = lo;
                if (hi_ok) {
                    *(float2*)(out_vposed + base + 2) = hi;
                    *(float2*)(out_naked  + base + 2) = hi;
                }
            }
        }
    }
}

// ---------------------------------------------------------------------------
// skinning (f32x2 + batch-tile 4): T = weights @ A2, verts = T*naked_h + trans
// block: 128 threads; thread: 2 vertices x 4 batches; blockIdx.y = batch group
// ---------------------------------------------------------------------------
__global__ __launch_bounds__(128) void skin_kernel(const float* __restrict__ trans,
                                                   const float* __restrict__ naked_in,
                                                   float* __restrict__ out_verts) {
    __shared__ __align__(16) float A2_s[SK_BT][NJ * 12];
    int bg = blockIdx.y;
    int b0 = bg * SK_BT;
    int tid = threadIdx.x;

    for (int i = tid; i < SK_BT * NJ * 12; i += 128) {
        int bb = i / (NJ * 12), e = i % (NJ * 12);
        A2_s[bb][e] = d_A2[(size_t)(b0 + bb) * NJ * 12 + e];
    }
    __syncthreads();

    int v0 = (blockIdx.x * 128 + tid) * 2;
    if (v0 >= NV) return;

    // acc[b][vi][pair e]: pair e covers T elements (2e, 2e+1)
    ull acc[SK_BT][2][6];
#pragma unroll
    for (int b = 0; b < SK_BT; b++)
#pragma unroll
        for (int vi = 0; vi < 2; vi++)
#pragma unroll
            for (int e = 0; e < 6; e++) acc[b][vi][e] = 0ULL;

    for (int j = 0; j < NJ; j++) {
        float2 w = *(const float2*)&d_wT[(size_t)j * NVP + v0];
        ull wx = splat2(w.x), wy = splat2(w.y);
#pragma unroll
        for (int b = 0; b < SK_BT; b++) {
            const ull* a2p = (const ull*)&A2_s[b][j * 12];
#pragma unroll
            for (int e = 0; e < 6; e++) {
                ull av = a2p[e];
                acc[b][0][e] = fma2(wx, av, acc[b][0][e]);
                acc[b][1][e] = fma2(wy, av, acc[b][1][e]);
            }
        }
    }

#pragma unroll
    for (int b = 0; b < SK_BT; b++) {
        int bglob = b0 + b;
        float tx = trans[bglob * 3 + 0], ty = trans[bglob * 3 + 1], tz = trans[bglob * 3 + 2];
#pragma unroll
        for (int vi = 0; vi < 2; vi++) {
            int v = v0 + vi;
            float2 t01 = unpack2(acc[b][vi][0]);
            float2 t23 = unpack2(acc[b][vi][1]);
            float2 t45 = unpack2(acc[b][vi][2]);
            float2 t67 = unpack2(acc[b][vi][3]);
            float2 t89 = unpack2(acc[b][vi][4]);
            float2 tab = unpack2(acc[b][vi][5]);
            size_t nb = (size_t)bglob * R3 + v * 3;
            float nx = naked_in[nb + 0], ny = naked_in[nb + 1], nz = naked_in[nb + 2];
            out_verts[nb + 0] = t01.x * nx + t01.y * ny + t23.x * nz + t23.y + tx;
            out_verts[nb + 1] = t45.x * nx + t45.y * ny + t67.x * nz + t67.y + ty;
            out_verts[nb + 2] = t89.x * nx + t89.y * ny + tab.x * nz + tab.y + tz;
        }
    }
}

// ---------------------------------------------------------------------------
extern "C" void kernel_launch(void* const* d_in, const int* in_sizes, int n_in,
                              void* d_out, int out_size) {
    (void)in_sizes; (void)n_in; (void)out_size;
    const float* pose  = (const float*)d_in[0];
    const float* betas = (const float*)d_in[1];
    const float* trans = (const float*)d_in[2];
    const float* vt    = (const float*)d_in[3];
    const float* sd    = (const float*)d_in[4];
    const float* pd    = (const float*)d_in[5];
    const float* Jreg  = (const float*)d_in[6];
    const float* wgt   = (const float*)d_in[7];

    float* out        = (float*)d_out;
    float* out_verts  = out;
    float* out_jtr    = out_verts + (size_t)BATCH * R3;
    float* out_vposed = out_jtr   + (size_t)BATCH * NJ * 3;
    float* out_naked  = out_vposed + (size_t)BATCH * R3;

    void *p_pdT, *p_sdT, *p_wT;
    cudaGetSymbolAddress(&p_pdT, d_pdT);
    cudaGetSymbolAddress(&p_sdT, d_sdT);
    cudaGetSymbolAddress(&p_wT,  d_wT);

    dim3 tb(32, 8);
    transpose_kernel<<<dim3((NP + 31) / 32, (R3 + 31) / 32), tb>>>(pd, (float*)p_pdT, R3, NP, RP);
    transpose_kernel<<<dim3((NB + 31) / 32, (R3 + 31) / 32), tb>>>(sd, (float*)p_sdT, R3, NB, RP);
    transpose_kernel<<<dim3((NJ + 31) / 32, (NV + 31) / 32), tb>>>(wgt, (float*)p_wT, NV, NJ, NVP);
    copy_vt_kernel<<<(R3 + 255) / 256, 256>>>(vt);

    jreg_kernel<<<NJ, 256>>>(Jreg, vt, sd);
    pose_kernel<<<BATCH, 64>>>(pose, betas, trans, out_jtr);

    naked_kernel<<<dim3(21, BATCH / C1_BT), 256>>>(betas, out_vposed, out_naked);
    skin_kernel<<<dim3((NV / 2 + 127) / 128, BATCH / SK_BT), 128>>>(trans, out_naked, out_verts);
}

// round 4
// speedup vs baseline: 1.4232x; 1.4139x over previous
#include <cuda_runtime.h>
#include <cuda_bf16.h>
#include <math.h>
#include <stdint.h>

typedef unsigned long long ull;

#define NJ 52
#define NV 6890
#define NB 10
#define NP 459            // (NJ-1)*9
#define BATCH 512
#define R3 20670          // NV*3
#define NVP 6912          // padded NV for transposed weights
#define SK_BT 4           // batches per block in skin
#define KC 480            // padded K: 459 pose + 10 betas + 1 vt + 10 pad
#define NKS (KC/16)       // 30 k-steps
#define MROWS 20736       // 162*128 padded rows

__constant__ int c_parents[NJ] = {
    -1,0,0,0,1,2,3,4,5,6,7,8,9,9,9,12,13,14,16,17,18,19,20,22,23,20,25,26,
    20,28,29,20,31,32,20,34,35,21,37,38,21,40,41,21,43,44,21,46,47,21,49,50};

// ---- scratch (__device__ globals: allocation-free) ----
__device__ __align__(16) __nv_bfloat16 d_RHi[(size_t)MROWS * KC];  // dirs rows hi (~20MB)
__device__ __align__(16) __nv_bfloat16 d_RLo[(size_t)MROWS * KC];
__device__ __align__(16) __nv_bfloat16 d_PHi[(size_t)BATCH * KC];  // batch rows hi
__device__ __align__(16) __nv_bfloat16 d_PLo[(size_t)BATCH * KC];
__device__ float d_wT [NJ * NVP];        // weights^T, padded
__device__ float d_A2 [BATCH * NJ * 12]; // A2 rows 0..2 (3x4 per joint)
__device__ float d_J0 [NJ * 3];
__device__ float d_Jsh[NJ * 3 * NB];

// ---------------- f32x2 packed-math helpers (skin kernel) -------------------
__device__ __forceinline__ ull fma2(ull a, ull b, ull c) {
    ull d;
    asm("fma.rn.f32x2 %0, %1, %2, %3;" : "=l"(d) : "l"(a), "l"(b), "l"(c));
    return d;
}
__device__ __forceinline__ ull splat2(float x) {
    ull r;
    asm("mov.b64 %0, {%1, %2};" : "=l"(r) : "f"(x), "f"(x));
    return r;
}
__device__ __forceinline__ float2 unpack2(ull u) {
    float2 f;
    asm("mov.b64 {%0, %1}, %2;" : "=f"(f.x), "=f"(f.y) : "l"(u));
    return f;
}

// ---------------- mma.sync / ldmatrix / cp.async helpers (plain sm_103) -----
__device__ __forceinline__ uint32_t smem_u32(const void* p) {
    uint32_t a;
    asm("{ .reg .u64 t; cvta.to.shared.u64 t, %1; cvt.u32.u64 %0, t; }" : "=r"(a) : "l"(p));
    return a;
}
__device__ __forceinline__ void ldsm4(uint32_t* r, uint32_t addr) {
    asm volatile("ldmatrix.sync.aligned.m8n8.x4.shared.b16 {%0,%1,%2,%3}, [%4];"
                 : "=r"(r[0]), "=r"(r[1]), "=r"(r[2]), "=r"(r[3]) : "r"(addr));
}
__device__ __forceinline__ void mma16816(float* d, const uint32_t* a, const uint32_t* b) {
    asm volatile("mma.sync.aligned.m16n8k16.row.col.f32.bf16.bf16.f32 "
                 "{%0,%1,%2,%3}, {%4,%5,%6,%7}, {%8,%9}, {%0,%1,%2,%3};"
                 : "+f"(d[0]), "+f"(d[1]), "+f"(d[2]), "+f"(d[3])
                 : "r"(a[0]), "r"(a[1]), "r"(a[2]), "r"(a[3]), "r"(b[0]), "r"(b[1]));
}
__device__ __forceinline__ void cpasync16(uint32_t dst, const void* src) {
    asm volatile("cp.async.cg.shared.global [%0], [%1], 16;" :: "r"(dst), "l"(src));
}
__device__ __forceinline__ void cpcommit() {
    asm volatile("cp.async.commit_group;" ::: "memory");
}
__device__ __forceinline__ void cpwait1() {
    asm volatile("cp.async.wait_group 1;" ::: "memory");
}
__device__ __forceinline__ void cpwait0() {
    asm volatile("cp.async.wait_group 0;" ::: "memory");
}

// ---------------------------------------------------------------------------
// convert R_cat = [posedirs | shapedirs | v_template | 0] -> bf16 hi/lo
// ---------------------------------------------------------------------------
__global__ void convertR_kernel(const float* __restrict__ pd,
                                const float* __restrict__ sd,
                                const float* __restrict__ vt) {
    int gid = blockIdx.x * 256 + threadIdx.x;   // MROWS*60 threads
    int r  = gid / 60;
    int k0 = (gid % 60) * 8;
    if (r >= MROWS) return;
    __align__(16) __nv_bfloat16 h[8];
    __align__(16) __nv_bfloat16 l[8];
#pragma unroll
    for (int t = 0; t < 8; t++) {
        int k = k0 + t;
        float x = 0.f;
        if (r < R3) {
            if (k < NP)            x = pd[(size_t)r * NP + k];
            else if (k < NP + NB)  x = sd[(size_t)r * NB + (k - NP)];
            else if (k == NP + NB) x = vt[r];
        }
        __nv_bfloat16 hh = __float2bfloat16(x);
        h[t] = hh;
        l[t] = __float2bfloat16(x - __bfloat162float(hh));
    }
    size_t o = (size_t)r * KC + k0;
    *(uint4*)&d_RHi[o] = *(uint4*)h;
    *(uint4*)&d_RLo[o] = *(uint4*)l;
}

// ---------------------------------------------------------------------------
// fold J_regressor: J0 = Jreg @ v_template, Jsh = Jreg @ shapedirs
// ---------------------------------------------------------------------------
__global__ void jreg_kernel(const float* __restrict__ Jreg,
                            const float* __restrict__ vt,
                            const float* __restrict__ sd) {
    int j = blockIdx.x;
    int tid = threadIdx.x;          // 256 threads
    float acc[33];
#pragma unroll
    for (int o = 0; o < 33; o++) acc[o] = 0.f;
    for (int v = tid; v < NV; v += 256) {
        float jr = Jreg[(size_t)j * NV + v];
#pragma unroll
        for (int k = 0; k < 3; k++) {
            acc[k] += jr * vt[v * 3 + k];
#pragma unroll
            for (int q = 0; q < NB; q++)
                acc[3 + k * NB + q] += jr * sd[(size_t)(v * 3 + k) * NB + q];
        }
    }
    __shared__ float red[256];
    for (int o = 0; o < 33; o++) {
        red[tid] = acc[o];
        __syncthreads();
        for (int s = 128; s > 0; s >>= 1) {
            if (tid < s) red[tid] += red[tid + s];
            __syncthreads();
        }
        if (tid == 0) {
            if (o < 3) d_J0[j * 3 + o] = red[0];
            else       d_Jsh[j * 30 + (o - 3)] = red[0];
        }
        __syncthreads();
    }
}

// ---------------------------------------------------------------------------
// per-batch: rodrigues, P_cat (bf16 hi/lo), th_j, kinematic chain, A2, th_jtr
// ---------------------------------------------------------------------------
__global__ void pose_kernel(const float* __restrict__ pose,
                            const float* __restrict__ betas,
                            const float* __restrict__ trans,
                            float* __restrict__ out_jtr) {
    int b = blockIdx.x;
    int tid = threadIdx.x;          // 64 threads
    __shared__ float rot_s[NJ][9];
    __shared__ float j_s[NJ][3];
    __shared__ float A_s[NJ][12];
    __shared__ float bet_s[NB];

    if (tid < NB) bet_s[tid] = betas[b * NB + tid];
    if (tid < NJ) {
        float x = pose[b * NJ * 3 + tid * 3 + 0];
        float y = pose[b * NJ * 3 + tid * 3 + 1];
        float z = pose[b * NJ * 3 + tid * 3 + 2];
        float th = sqrtf(x * x + y * y + z * z + 1e-8f);
        float inv = 1.f / th;
        float kx = x * inv, ky = y * inv, kz = z * inv;
        float s = sinf(th), c = cosf(th), oc = 1.f - c;
        rot_s[tid][0] = c + oc * kx * kx;
        rot_s[tid][1] = -s * kz + oc * kx * ky;
        rot_s[tid][2] =  s * ky + oc * kx * kz;
        rot_s[tid][3] =  s * kz + oc * ky * kx;
        rot_s[tid][4] = c + oc * ky * ky;
        rot_s[tid][5] = -s * kx + oc * ky * kz;
        rot_s[tid][6] = -s * ky + oc * kz * kx;
        rot_s[tid][7] =  s * kx + oc * kz * ky;
        rot_s[tid][8] = c + oc * kz * kz;
    }
    __syncthreads();

    // th_j = J0 + Jsh @ betas
    for (int idx = tid; idx < NJ * 3; idx += 64) {
        int j = idx / 3, k = idx % 3;
        float v = d_J0[idx];
#pragma unroll
        for (int q = 0; q < NB; q++)
            v += d_Jsh[j * 30 + k * NB + q] * bet_s[q];
        j_s[j][k] = v;
    }
    // P_cat = [pose_map | betas | 1 | 0] as bf16 hi/lo
    for (int k = tid; k < KC; k += 64) {
        float x;
        if (k < NP) {
            int j = k / 9 + 1, e = k % 9;
            float iv = (e == 0 || e == 4 || e == 8) ? 1.f : 0.f;
            x = rot_s[j][e] - iv;
        } else if (k < NP + NB) {
            x = bet_s[k - NP];
        } else if (k == NP + NB) {
            x = 1.f;
        } else {
            x = 0.f;
        }
        __nv_bfloat16 hh = __float2bfloat16(x);
        d_PHi[(size_t)b * KC + k] = hh;
        d_PLo[(size_t)b * KC + k] = __float2bfloat16(x - __bfloat162float(hh));
    }
    __syncthreads();

    if (tid == 0) {
#pragma unroll
        for (int m = 0; m < 3; m++) {
#pragma unroll
            for (int n = 0; n < 3; n++) A_s[0][m * 4 + n] = rot_s[0][m * 3 + n];
            A_s[0][m * 4 + 3] = j_s[0][m];
        }
        for (int i = 1; i < NJ; i++) {
            int p = c_parents[i];
            float t0 = j_s[i][0] - j_s[p][0];
            float t1 = j_s[i][1] - j_s[p][1];
            float t2 = j_s[i][2] - j_s[p][2];
#pragma unroll
            for (int m = 0; m < 3; m++) {
                float r0 = A_s[p][m * 4 + 0], r1 = A_s[p][m * 4 + 1], r2 = A_s[p][m * 4 + 2];
#pragma unroll
                for (int n = 0; n < 3; n++)
                    A_s[i][m * 4 + n] = r0 * rot_s[i][0 * 3 + n] + r1 * rot_s[i][1 * 3 + n] + r2 * rot_s[i][2 * 3 + n];
                A_s[i][m * 4 + 3] = r0 * t0 + r1 * t1 + r2 * t2 + A_s[p][m * 4 + 3];
            }
        }
    }
    __syncthreads();

    for (int idx = tid; idx < NJ * 3; idx += 64) {
        int j = idx / 3, m = idx % 3;
        float r0 = A_s[j][m * 4 + 0], r1 = A_s[j][m * 4 + 1], r2 = A_s[j][m * 4 + 2];
        float t  = A_s[j][m * 4 + 3];
        float tmp = r0 * j_s[j][0] + r1 * j_s[j][1] + r2 * j_s[j][2];
        float* a2 = &d_A2[((size_t)b * NJ + j) * 12 + m * 4];
        a2[0] = r0; a2[1] = r1; a2[2] = r2; a2[3] = t - tmp;
        out_jtr[(size_t)b * NJ * 3 + j * 3 + m] = t + trans[b * 3 + m];
    }
}

// ---------------------------------------------------------------------------
// naked GEMM via mma.sync bf16x3: out[64 batches x 128 rows] per block
// grid (162 row-tiles, 8 batch-tiles), 128 threads / 4 warps
// ---------------------------------------------------------------------------
__global__ __launch_bounds__(128) void mma_naked_kernel(float* __restrict__ out_vposed,
                                                        float* __restrict__ out_naked) {
    // smem stages: row stride 24 bf16 (48B) -> conflict-free ldmatrix
    __shared__ __nv_bfloat16 sBatHi[2][64][24];
    __shared__ __nv_bfloat16 sBatLo[2][64][24];
    __shared__ __nv_bfloat16 sRowHi[2][128][24];
    __shared__ __nv_bfloat16 sRowLo[2][128][24];

    const int tid  = threadIdx.x;
    const int wid  = tid >> 5;
    const int lane = tid & 31;
    const int r0 = blockIdx.x * 128;   // dirs rows
    const int b0 = blockIdx.y * 64;    // batches

    // ---- cp.async source/dest precompute (6 ops per thread) ----
    const int crow = tid >> 1;         // 0..63
    const int chalf = (tid & 1) * 8;
    uint32_t dA_hi = smem_u32(&sBatHi[0][crow][chalf]);
    uint32_t dA_lo = smem_u32(&sBatLo[0][crow][chalf]);
    uint32_t dR_hi0 = smem_u32(&sRowHi[0][crow][chalf]);
    uint32_t dR_hi1 = smem_u32(&sRowHi[0][64 + crow][chalf]);
    uint32_t dR_lo0 = smem_u32(&sRowLo[0][crow][chalf]);
    uint32_t dR_lo1 = smem_u32(&sRowLo[0][64 + crow][chalf]);
    const __nv_bfloat16* sP_hi = d_PHi + (size_t)(b0 + crow) * KC + chalf;
    const __nv_bfloat16* sP_lo = d_PLo + (size_t)(b0 + crow) * KC + chalf;
    const __nv_bfloat16* sR_hi0 = d_RHi + (size_t)(r0 + crow) * KC + chalf;
    const __nv_bfloat16* sR_hi1 = d_RHi + (size_t)(r0 + 64 + crow) * KC + chalf;
    const __nv_bfloat16* sR_lo0 = d_RLo + (size_t)(r0 + crow) * KC + chalf;
    const __nv_bfloat16* sR_lo1 = d_RLo + (size_t)(r0 + 64 + crow) * KC + chalf;
    const uint32_t stA = 64 * 24 * 2;    // 3072 bytes per stage
    const uint32_t stR = 128 * 24 * 2;   // 6144 bytes per stage

    // ---- ldmatrix per-lane offsets (bytes, stage 0) ----
    // A operand (batch m16k16): lanes0-15 row lane col0; 16-31 row lane-16 col8
    uint32_t offA = (uint32_t)(((wid * 16 + (lane & 15)) * 24 + (lane >> 4) * 8) * 2);
    uint32_t aHiBase = smem_u32(&sBatHi[0][0][0]) + offA;
    uint32_t aLoBase = smem_u32(&sBatLo[0][0][0]) + offA;
    // B operand (rows n16k16 per group): row=(lane&7)+((lane>>4)&1)*8, col=((lane>>3)&1)*8
    uint32_t offB = (uint32_t)((((lane & 7) + ((lane >> 4) & 1) * 8) * 24 + ((lane >> 3) & 1) * 8) * 2);
    uint32_t bHiBase = smem_u32(&sRowHi[0][0][0]) + offB;
    uint32_t bLoBase = smem_u32(&sRowLo[0][0][0]) + offB;

    float d[16][4];
#pragma unroll
    for (int i = 0; i < 16; i++)
#pragma unroll
        for (int j = 0; j < 4; j++) d[i][j] = 0.f;

    // prologue: stage 0
    {
        cpasync16(dA_hi, sP_hi);  cpasync16(dA_lo, sP_lo);
        cpasync16(dR_hi0, sR_hi0); cpasync16(dR_hi1, sR_hi1);
        cpasync16(dR_lo0, sR_lo0); cpasync16(dR_lo1, sR_lo1);
        cpcommit();
    }

    for (int ks = 0; ks < NKS; ks++) {
        if (ks + 1 < NKS) {
            uint32_t so = ((ks + 1) & 1);
            uint32_t aoff = so * stA, roff = so * stR;
            int koff = (ks + 1) * 16;
            cpasync16(dA_hi + aoff, sP_hi + koff);
            cpasync16(dA_lo + aoff, sP_lo + koff);
            cpasync16(dR_hi0 + roff, sR_hi0 + koff);
            cpasync16(dR_hi1 + roff, sR_hi1 + koff);
            cpasync16(dR_lo0 + roff, sR_lo0 + koff);
            cpasync16(dR_lo1 + roff, sR_lo1 + koff);
            cpcommit();
            cpwait1();
        } else {
            cpwait0();
        }
        __syncthreads();

        uint32_t st = ks & 1;
        uint32_t ahi[4], alo[4];
        ldsm4(ahi, aHiBase + st * stA);
        ldsm4(alo, aLoBase + st * stA);
#pragma unroll
        for (int g = 0; g < 8; g++) {
            uint32_t bhi[4], blo[4];
            ldsm4(bhi, bHiBase + st * stR + g * 768);   // 16 rows * 48B = 768
            ldsm4(blo, bLoBase + st * stR + g * 768);
            mma16816(d[2 * g],     ahi, bhi);
            mma16816(d[2 * g],     ahi, blo);
            mma16816(d[2 * g],     alo, bhi);
            mma16816(d[2 * g + 1], ahi, bhi + 2);
            mma16816(d[2 * g + 1], ahi, blo + 2);
            mma16816(d[2 * g + 1], alo, bhi + 2);
        }
        __syncthreads();
    }

    // epilogue: d[nt] c0,c1 -> (m = b0+wid*16+(lane>>2), n = r0+nt*8+(lane&3)*2)
    //           c2,c3 -> m+8
    int m = b0 + wid * 16 + (lane >> 2);
#pragma unroll
    for (int nt = 0; nt < 16; nt++) {
        int n = r0 + nt * 8 + (lane & 3) * 2;
        if (n < R3) {
            size_t o1 = (size_t)m * R3 + n;
            size_t o2 = (size_t)(m + 8) * R3 + n;
            float2 v01 = make_float2(d[nt][0], d[nt][1]);
            float2 v23 = make_float2(d[nt][2], d[nt][3]);
            *(float2*)(out_vposed + o1) = v01;
            *(float2*)(out_naked  + o1) = v01;
            *(float2*)(out_vposed + o2) = v23;
            *(float2*)(out_naked  + o2) = v23;
        }
    }
}

// ---------------------------------------------------------------------------
// transpose weights (NV x NJ) -> (NJ x NVP)
// ---------------------------------------------------------------------------
__global__ void transpose_kernel(const float* __restrict__ in, float* __restrict__ out,
                                 int M, int N, int ldOut) {
    __shared__ float tile[32][33];
    int c0 = blockIdx.x * 32;
    int r0 = blockIdx.y * 32;
    int tx = threadIdx.x, ty = threadIdx.y;   // block (32,8)
#pragma unroll
    for (int i = 0; i < 32; i += 8) {
        int r = r0 + ty + i, c = c0 + tx;
        tile[ty + i][tx] = (r < M && c < N) ? in[(size_t)r * N + c] : 0.f;
    }
    __syncthreads();
#pragma unroll
    for (int i = 0; i < 32; i += 8) {
        int c = c0 + ty + i, r = r0 + tx;
        if (c < N && r < ldOut)
            out[(size_t)c * ldOut + r] = tile[tx][ty + i];
    }
}

// ---------------------------------------------------------------------------
// skinning (f32x2 + batch-tile 4): T = weights @ A2, verts = T*naked_h + trans
// ---------------------------------------------------------------------------
__global__ __launch_bounds__(128) void skin_kernel(const float* __restrict__ trans,
                                                   const float* __restrict__ naked_in,
                                                   float* __restrict__ out_verts) {
    __shared__ __align__(16) float A2_s[SK_BT][NJ * 12];
    int bg = blockIdx.y;
    int b0 = bg * SK_BT;
    int tid = threadIdx.x;

    for (int i = tid; i < SK_BT * NJ * 12; i += 128) {
        int bb = i / (NJ * 12), e = i % (NJ * 12);
        A2_s[bb][e] = d_A2[(size_t)(b0 + bb) * NJ * 12 + e];
    }
    __syncthreads();

    int v0 = (blockIdx.x * 128 + tid) * 2;
    if (v0 >= NV) return;

    ull acc[SK_BT][2][6];
#pragma unroll
    for (int b = 0; b < SK_BT; b++)
#pragma unroll
        for (int vi = 0; vi < 2; vi++)
#pragma unroll
            for (int e = 0; e < 6; e++) acc[b][vi][e] = 0ULL;

    for (int j = 0; j < NJ; j++) {
        float2 w = *(const float2*)&d_wT[(size_t)j * NVP + v0];
        ull wx = splat2(w.x), wy = splat2(w.y);
#pragma unroll
        for (int b = 0; b < SK_BT; b++) {
            const ull* a2p = (const ull*)&A2_s[b][j * 12];
#pragma unroll
            for (int e = 0; e < 6; e++) {
                ull av = a2p[e];
                acc[b][0][e] = fma2(wx, av, acc[b][0][e]);
                acc[b][1][e] = fma2(wy, av, acc[b][1][e]);
            }
        }
    }

#pragma unroll
    for (int b = 0; b < SK_BT; b++) {
        int bglob = b0 + b;
        float tx = trans[bglob * 3 + 0], ty = trans[bglob * 3 + 1], tz = trans[bglob * 3 + 2];
#pragma unroll
        for (int vi = 0; vi < 2; vi++) {
            int v = v0 + vi;
            float2 t01 = unpack2(acc[b][vi][0]);
            float2 t23 = unpack2(acc[b][vi][1]);
            float2 t45 = unpack2(acc[b][vi][2]);
            float2 t67 = unpack2(acc[b][vi][3]);
            float2 t89 = unpack2(acc[b][vi][4]);
            float2 tab = unpack2(acc[b][vi][5]);
            size_t nb = (size_t)bglob * R3 + v * 3;
            float nx = naked_in[nb + 0], ny = naked_in[nb + 1], nz = naked_in[nb + 2];
            out_verts[nb + 0] = t01.x * nx + t01.y * ny + t23.x * nz + t23.y + tx;
            out_verts[nb + 1] = t45.x * nx + t45.y * ny + t67.x * nz + t67.y + ty;
            out_verts[nb + 2] = t89.x * nx + t89.y * ny + tab.x * nz + tab.y + tz;
        }
    }
}

// ---------------------------------------------------------------------------
extern "C" void kernel_launch(void* const* d_in, const int* in_sizes, int n_in,
                              void* d_out, int out_size) {
    (void)in_sizes; (void)n_in; (void)out_size;
    const float* pose  = (const float*)d_in[0];
    const float* betas = (const float*)d_in[1];
    const float* trans = (const float*)d_in[2];
    const float* vt    = (const float*)d_in[3];
    const float* sd    = (const float*)d_in[4];
    const float* pd    = (const float*)d_in[5];
    const float* Jreg  = (const float*)d_in[6];
    const float* wgt   = (const float*)d_in[7];

    float* out        = (float*)d_out;
    float* out_verts  = out;
    float* out_jtr    = out_verts + (size_t)BATCH * R3;
    float* out_vposed = out_jtr   + (size_t)BATCH * NJ * 3;
    float* out_naked  = out_vposed + (size_t)BATCH * R3;

    void* p_wT;
    cudaGetSymbolAddress(&p_wT, d_wT);

    int convThreads = MROWS * 60;
    convertR_kernel<<<(convThreads + 255) / 256, 256>>>(pd, sd, vt);              // 0
    jreg_kernel<<<NJ, 256>>>(Jreg, vt, sd);                                       // 1
    pose_kernel<<<BATCH, 64>>>(pose, betas, trans, out_jtr);                      // 2
    mma_naked_kernel<<<dim3(162, 8), 128>>>(out_vposed, out_naked);               // 3
    dim3 tb(32, 8);
    transpose_kernel<<<dim3((NJ + 31) / 32, (NV + 31) / 32), tb>>>(wgt, (float*)p_wT, NV, NJ, NVP); // 4
    skin_kernel<<<dim3((NV / 2 + 127) / 128, BATCH / SK_BT), 128>>>(trans, out_naked, out_verts);   // 5
}

// round 6
// speedup vs baseline: 1.5889x; 1.1164x over previous
#include <cuda_runtime.h>
#include <cuda_bf16.h>
#include <math.h>
#include <stdint.h>

typedef unsigned long long ull;

#define NJ 52
#define NV 6890
#define NB 10
#define NP 459            // (NJ-1)*9
#define BATCH 512
#define R3 20670          // NV*3
#define NVP 6912          // padded NV for transposed weights
#define SK_BT 2           // batches per block in skin
#define KC 480            // padded K: 459 pose + 10 betas + 1 vt + 10 pad
#define NKS (KC/16)       // 30 k-steps
#define MROWS 20736       // 162*128 padded rows

__constant__ int c_parents[NJ] = {
    -1,0,0,0,1,2,3,4,5,6,7,8,9,9,9,12,13,14,16,17,18,19,20,22,23,20,25,26,
    20,28,29,20,31,32,20,34,35,21,37,38,21,40,41,21,43,44,21,46,47,21,49,50};

// ---- scratch (__device__ globals: allocation-free) ----
__device__ __align__(16) __nv_bfloat16 d_RHi[(size_t)MROWS * KC];  // dirs rows hi (~20MB)
__device__ __align__(16) __nv_bfloat16 d_RLo[(size_t)MROWS * KC];
__device__ __align__(16) __nv_bfloat16 d_PHi[(size_t)BATCH * KC];  // batch rows hi
__device__ __align__(16) __nv_bfloat16 d_PLo[(size_t)BATCH * KC];
__device__ float d_wT [NJ * NVP];        // weights^T, padded
__device__ float d_A2 [BATCH * NJ * 12]; // A2 rows 0..2 (3x4 per joint)
__device__ float d_J0 [NJ * 3];
__device__ float d_Jsh[NJ * 3 * NB];

// ---------------- f32x2 packed-math helpers (skin kernel) -------------------
__device__ __forceinline__ ull fma2(ull a, ull b, ull c) {
    ull d;
    asm("fma.rn.f32x2 %0, %1, %2, %3;" : "=l"(d) : "l"(a), "l"(b), "l"(c));
    return d;
}
__device__ __forceinline__ ull splat2(float x) {
    ull r;
    asm("mov.b64 %0, {%1, %2};" : "=l"(r) : "f"(x), "f"(x));
    return r;
}
__device__ __forceinline__ float2 unpack2(ull u) {
    float2 f;
    asm("mov.b64 {%0, %1}, %2;" : "=f"(f.x), "=f"(f.y) : "l"(u));
    return f;
}

// ---------------- mma.sync / ldmatrix / cp.async helpers (plain sm_103) -----
__device__ __forceinline__ uint32_t smem_u32(const void* p) {
    uint32_t a;
    asm("{ .reg .u64 t; cvta.to.shared.u64 t, %1; cvt.u32.u64 %0, t; }" : "=r"(a) : "l"(p));
    return a;
}
__device__ __forceinline__ void ldsm4(uint32_t* r, uint32_t addr) {
    asm volatile("ldmatrix.sync.aligned.m8n8.x4.shared.b16 {%0,%1,%2,%3}, [%4];"
                 : "=r"(r[0]), "=r"(r[1]), "=r"(r[2]), "=r"(r[3]) : "r"(addr));
}
__device__ __forceinline__ void mma16816(float* d, const uint32_t* a, const uint32_t* b) {
    asm volatile("mma.sync.aligned.m16n8k16.row.col.f32.bf16.bf16.f32 "
                 "{%0,%1,%2,%3}, {%4,%5,%6,%7}, {%8,%9}, {%0,%1,%2,%3};"
                 : "+f"(d[0]), "+f"(d[1]), "+f"(d[2]), "+f"(d[3])
                 : "r"(a[0]), "r"(a[1]), "r"(a[2]), "r"(a[3]), "r"(b[0]), "r"(b[1]));
}
__device__ __forceinline__ void cpasync16(uint32_t dst, const void* src) {
    asm volatile("cp.async.cg.shared.global [%0], [%1], 16;" :: "r"(dst), "l"(src));
}
__device__ __forceinline__ void cpcommit() {
    asm volatile("cp.async.commit_group;" ::: "memory");
}
__device__ __forceinline__ void cpwait1() {
    asm volatile("cp.async.wait_group 1;" ::: "memory");
}
__device__ __forceinline__ void cpwait0() {
    asm volatile("cp.async.wait_group 0;" ::: "memory");
}

// ---------------------------------------------------------------------------
// convert R_cat = [posedirs | shapedirs | v_template | 0] -> bf16 hi/lo
// ---------------------------------------------------------------------------
__global__ void convertR_kernel(const float* __restrict__ pd,
                                const float* __restrict__ sd,
                                const float* __restrict__ vt) {
    int gid = blockIdx.x * 256 + threadIdx.x;   // MROWS*60 threads
    int r  = gid / 60;
    int k0 = (gid % 60) * 8;
    if (r >= MROWS) return;
    __align__(16) __nv_bfloat16 h[8];
    __align__(16) __nv_bfloat16 l[8];
#pragma unroll
    for (int t = 0; t < 8; t++) {
        int k = k0 + t;
        float x = 0.f;
        if (r < R3) {
            if (k < NP)            x = pd[(size_t)r * NP + k];
            else if (k < NP + NB)  x = sd[(size_t)r * NB + (k - NP)];
            else if (k == NP + NB) x = vt[r];
        }
        __nv_bfloat16 hh = __float2bfloat16(x);
        h[t] = hh;
        l[t] = __float2bfloat16(x - __bfloat162float(hh));
    }
    size_t o = (size_t)r * KC + k0;
    *(uint4*)&d_RHi[o] = *(uint4*)h;
    *(uint4*)&d_RLo[o] = *(uint4*)l;
}

// ---------------------------------------------------------------------------
// fold J_regressor: J0 = Jreg @ v_template, Jsh = Jreg @ shapedirs
// ---------------------------------------------------------------------------
__global__ void jreg_kernel(const float* __restrict__ Jreg,
                            const float* __restrict__ vt,
                            const float* __restrict__ sd) {
    int j = blockIdx.x;
    int tid = threadIdx.x;          // 256 threads
    float acc[33];
#pragma unroll
    for (int o = 0; o < 33; o++) acc[o] = 0.f;
    for (int v = tid; v < NV; v += 256) {
        float jr = Jreg[(size_t)j * NV + v];
#pragma unroll
        for (int k = 0; k < 3; k++) {
            acc[k] += jr * vt[v * 3 + k];
#pragma unroll
            for (int q = 0; q < NB; q++)
                acc[3 + k * NB + q] += jr * sd[(size_t)(v * 3 + k) * NB + q];
        }
    }
    __shared__ float red[256];
    for (int o = 0; o < 33; o++) {
        red[tid] = acc[o];
        __syncthreads();
        for (int s = 128; s > 0; s >>= 1) {
            if (tid < s) red[tid] += red[tid + s];
            __syncthreads();
        }
        if (tid == 0) {
            if (o < 3) d_J0[j * 3 + o] = red[0];
            else       d_Jsh[j * 30 + (o - 3)] = red[0];
        }
        __syncthreads();
    }
}

// ---------------------------------------------------------------------------
// per-batch: rodrigues, P_cat (bf16 hi/lo), th_j, kinematic chain, A2, th_jtr
// ---------------------------------------------------------------------------
__global__ void pose_kernel(const float* __restrict__ pose,
                            const float* __restrict__ betas,
                            const float* __restrict__ trans,
                            float* __restrict__ out_jtr) {
    int b = blockIdx.x;
    int tid = threadIdx.x;          // 64 threads
    __shared__ float rot_s[NJ][9];
    __shared__ float j_s[NJ][3];
    __shared__ float A_s[NJ][12];
    __shared__ float bet_s[NB];

    if (tid < NB) bet_s[tid] = betas[b * NB + tid];
    if (tid < NJ) {
        float x = pose[b * NJ * 3 + tid * 3 + 0];
        float y = pose[b * NJ * 3 + tid * 3 + 1];
        float z = pose[b * NJ * 3 + tid * 3 + 2];
        float th = sqrtf(x * x + y * y + z * z + 1e-8f);
        float inv = 1.f / th;
        float kx = x * inv, ky = y * inv, kz = z * inv;
        float s = sinf(th), c = cosf(th), oc = 1.f - c;
        rot_s[tid][0] = c + oc * kx * kx;
        rot_s[tid][1] = -s * kz + oc * kx * ky;
        rot_s[tid][2] =  s * ky + oc * kx * kz;
        rot_s[tid][3] =  s * kz + oc * ky * kx;
        rot_s[tid][4] = c + oc * ky * ky;
        rot_s[tid][5] = -s * kx + oc * ky * kz;
        rot_s[tid][6] = -s * ky + oc * kz * kx;
        rot_s[tid][7] =  s * kx + oc * kz * ky;
        rot_s[tid][8] = c + oc * kz * kz;
    }
    __syncthreads();

    // th_j = J0 + Jsh @ betas
    for (int idx = tid; idx < NJ * 3; idx += 64) {
        int j = idx / 3, k = idx % 3;
        float v = d_J0[idx];
#pragma unroll
        for (int q = 0; q < NB; q++)
            v += d_Jsh[j * 30 + k * NB + q] * bet_s[q];
        j_s[j][k] = v;
    }
    // P_cat = [pose_map | betas | 1 | 0] as bf16 hi/lo
    for (int k = tid; k < KC; k += 64) {
        float x;
        if (k < NP) {
            int j = k / 9 + 1, e = k % 9;
            float iv = (e == 0 || e == 4 || e == 8) ? 1.f : 0.f;
            x = rot_s[j][e] - iv;
        } else if (k < NP + NB) {
            x = bet_s[k - NP];
        } else if (k == NP + NB) {
            x = 1.f;
        } else {
            x = 0.f;
        }
        __nv_bfloat16 hh = __float2bfloat16(x);
        d_PHi[(size_t)b * KC + k] = hh;
        d_PLo[(size_t)b * KC + k] = __float2bfloat16(x - __bfloat162float(hh));
    }
    __syncthreads();

    if (tid == 0) {
#pragma unroll
        for (int m = 0; m < 3; m++) {
#pragma unroll
            for (int n = 0; n < 3; n++) A_s[0][m * 4 + n] = rot_s[0][m * 3 + n];
            A_s[0][m * 4 + 3] = j_s[0][m];
        }
        for (int i = 1; i < NJ; i++) {
            int p = c_parents[i];
            float t0 = j_s[i][0] - j_s[p][0];
            float t1 = j_s[i][1] - j_s[p][1];
            float t2 = j_s[i][2] - j_s[p][2];
#pragma unroll
            for (int m = 0; m < 3; m++) {
                float r0 = A_s[p][m * 4 + 0], r1 = A_s[p][m * 4 + 1], r2 = A_s[p][m * 4 + 2];
#pragma unroll
                for (int n = 0; n < 3; n++)
                    A_s[i][m * 4 + n] = r0 * rot_s[i][0 * 3 + n] + r1 * rot_s[i][1 * 3 + n] + r2 * rot_s[i][2 * 3 + n];
                A_s[i][m * 4 + 3] = r0 * t0 + r1 * t1 + r2 * t2 + A_s[p][m * 4 + 3];
            }
        }
    }
    __syncthreads();

    for (int idx = tid; idx < NJ * 3; idx += 64) {
        int j = idx / 3, m = idx % 3;
        float r0 = A_s[j][m * 4 + 0], r1 = A_s[j][m * 4 + 1], r2 = A_s[j][m * 4 + 2];
        float t  = A_s[j][m * 4 + 3];
        float tmp = r0 * j_s[j][0] + r1 * j_s[j][1] + r2 * j_s[j][2];
        float* a2 = &d_A2[((size_t)b * NJ + j) * 12 + m * 4];
        a2[0] = r0; a2[1] = r1; a2[2] = r2; a2[3] = t - tmp;
        out_jtr[(size_t)b * NJ * 3 + j * 3 + m] = t + trans[b * 3 + m];
    }
}

// ---------------------------------------------------------------------------
// naked GEMM via mma.sync bf16x3: block tile 128 batches x 128 rows
// 256 threads / 8 warps as 2(m) x 4(n); warp tile m64 x n32
// ---------------------------------------------------------------------------
__global__ __launch_bounds__(256) void mma_naked_kernel(float* __restrict__ out_vposed,
                                                        float* __restrict__ out_naked) {
    // stage stride 24 bf16 (48B) rows -> conflict-free ldmatrix
    __shared__ __align__(16) __nv_bfloat16 sAHi[2][128 * 24];
    __shared__ __align__(16) __nv_bfloat16 sALo[2][128 * 24];
    __shared__ __align__(16) __nv_bfloat16 sBHi[2][128 * 24];
    __shared__ __align__(16) __nv_bfloat16 sBLo[2][128 * 24];

    const int tid  = threadIdx.x;
    const int wid  = tid >> 5;
    const int lane = tid & 31;
    const int wm = wid & 1;      // warp m index (0..1)
    const int wn = wid >> 1;     // warp n index (0..3)
    const int r0 = blockIdx.x * 128;   // dirs rows
    const int b0 = blockIdx.y * 128;   // batches
    const uint32_t STG = 128 * 24 * 2; // 6144 bytes per stage

    // ---- cp.async: thread covers one (row, 16B-chunk) per buffer ----
    const int crow = tid >> 1;         // 0..127
    const int cch  = tid & 1;
    const uint32_t dstoff = (uint32_t)(crow * 48 + cch * 16);
    uint32_t dA_hi = smem_u32(sAHi) + dstoff;
    uint32_t dA_lo = smem_u32(sALo) + dstoff;
    uint32_t dB_hi = smem_u32(sBHi) + dstoff;
    uint32_t dB_lo = smem_u32(sBLo) + dstoff;
    const __nv_bfloat16* sP_hi = d_PHi + (size_t)(b0 + crow) * KC + cch * 8;
    const __nv_bfloat16* sP_lo = d_PLo + (size_t)(b0 + crow) * KC + cch * 8;
    const __nv_bfloat16* sR_hi = d_RHi + (size_t)(r0 + crow) * KC + cch * 8;
    const __nv_bfloat16* sR_lo = d_RLo + (size_t)(r0 + crow) * KC + cch * 8;

    // ---- ldmatrix per-lane byte offsets within a stage ----
    uint32_t offA = (uint32_t)((wm * 64 + (lane & 15)) * 48 + (lane >> 4) * 16);
    uint32_t offB = (uint32_t)((wn * 32 + (lane & 7) + ((lane >> 4) & 1) * 8) * 48
                               + ((lane >> 3) & 1) * 16);
    uint32_t aHiB = smem_u32(sAHi) + offA;
    uint32_t aLoB = smem_u32(sALo) + offA;
    uint32_t bHiB = smem_u32(sBHi) + offB;
    uint32_t bLoB = smem_u32(sBLo) + offB;

    float d[4][4][4];   // [mtile][n8-tile][frag]
#pragma unroll
    for (int i = 0; i < 4; i++)
#pragma unroll
        for (int j = 0; j < 4; j++)
#pragma unroll
            for (int k = 0; k < 4; k++) d[i][j][k] = 0.f;

    // prologue: stage 0
    cpasync16(dA_hi, sP_hi);
    cpasync16(dA_lo, sP_lo);
    cpasync16(dB_hi, sR_hi);
    cpasync16(dB_lo, sR_lo);
    cpcommit();

    for (int ks = 0; ks < NKS; ks++) {
        if (ks + 1 < NKS) {
            uint32_t so = ((ks + 1) & 1) * STG;
            int koff = (ks + 1) * 16;
            cpasync16(dA_hi + so, sP_hi + koff);
            cpasync16(dA_lo + so, sP_lo + koff);
            cpasync16(dB_hi + so, sR_hi + koff);
            cpasync16(dB_lo + so, sR_lo + koff);
            cpcommit();
            cpwait1();
        } else {
            cpwait0();
        }
        __syncthreads();

        uint32_t st = (ks & 1) * STG;
        uint32_t bh[2][4], bl[2][4];
        ldsm4(bh[0], bHiB + st);
        ldsm4(bh[1], bHiB + st + 768);
        ldsm4(bl[0], bLoB + st);
        ldsm4(bl[1], bLoB + st + 768);
#pragma unroll
        for (int mi = 0; mi < 4; mi++) {
            uint32_t ah[4], al[4];
            ldsm4(ah, aHiB + st + mi * 768);
            ldsm4(al, aLoB + st + mi * 768);
#pragma unroll
            for (int g = 0; g < 2; g++) {
                mma16816(d[mi][2 * g],     ah, bh[g]);
                mma16816(d[mi][2 * g],     ah, bl[g]);
                mma16816(d[mi][2 * g],     al, bh[g]);
                mma16816(d[mi][2 * g + 1], ah, bh[g] + 2);
                mma16816(d[mi][2 * g + 1], ah, bl[g] + 2);
                mma16816(d[mi][2 * g + 1], al, bh[g] + 2);
            }
        }
        __syncthreads();
    }

    // epilogue: lane frag (c0,c1)->(m,n), (c2,c3)->(m+8,n)
    int mbase = b0 + wm * 64 + (lane >> 2);
    int nbase = r0 + wn * 32 + (lane & 3) * 2;
#pragma unroll
    for (int mi = 0; mi < 4; mi++) {
        int m = mbase + mi * 16;
#pragma unroll
        for (int t = 0; t < 4; t++) {
            int n = nbase + t * 8;
            if (n < R3) {
                size_t o1 = (size_t)m * R3 + n;
                size_t o2 = (size_t)(m + 8) * R3 + n;
                float2 v01 = make_float2(d[mi][t][0], d[mi][t][1]);
                float2 v23 = make_float2(d[mi][t][2], d[mi][t][3]);
                *(float2*)(out_vposed + o1) = v01;
                *(float2*)(out_naked  + o1) = v01;
                *(float2*)(out_vposed + o2) = v23;
                *(float2*)(out_naked  + o2) = v23;
            }
        }
    }
}

// ---------------------------------------------------------------------------
// transpose weights (NV x NJ) -> (NJ x NVP)
// ---------------------------------------------------------------------------
__global__ void transpose_kernel(const float* __restrict__ in, float* __restrict__ out,
                                 int M, int N, int ldOut) {
    __shared__ float tile[32][33];
    int c0 = blockIdx.x * 32;
    int r0 = blockIdx.y * 32;
    int tx = threadIdx.x, ty = threadIdx.y;   // block (32,8)
#pragma unroll
    for (int i = 0; i < 32; i += 8) {
        int r = r0 + ty + i, c = c0 + tx;
        tile[ty + i][tx] = (r < M && c < N) ? in[(size_t)r * N + c] : 0.f;
    }
    __syncthreads();
#pragma unroll
    for (int i = 0; i < 32; i += 8) {
        int c = c0 + ty + i, r = r0 + tx;
        if (c < N && r < ldOut)
            out[(size_t)c * ldOut + r] = tile[tx][ty + i];
    }
}

// ---------------------------------------------------------------------------
// skinning: 4 verts x 2 batches per thread, f32x2 math, float2 I/O
// (float2 only: base = b*R3 + v0*3 is 8B-aligned but NOT 16B-aligned for odd b)
// ---------------------------------------------------------------------------
__global__ __launch_bounds__(128) void skin_kernel(const float* __restrict__ trans,
                                                   const float* __restrict__ naked_in,
                                                   float* __restrict__ out_verts) {
    __shared__ __align__(16) float A2_s[SK_BT][NJ * 12];
    int b0 = blockIdx.y * SK_BT;
    int tid = threadIdx.x;

    for (int i = tid; i < SK_BT * NJ * 12; i += 128) {
        int bb = i / (NJ * 12), e = i % (NJ * 12);
        A2_s[bb][e] = d_A2[(size_t)(b0 + bb) * NJ * 12 + e];
    }
    __syncthreads();

    int v0 = (blockIdx.x * 128 + tid) * 4;
    if (v0 >= NV) return;

    ull acc[SK_BT][4][6];
#pragma unroll
    for (int b = 0; b < SK_BT; b++)
#pragma unroll
        for (int vi = 0; vi < 4; vi++)
#pragma unroll
            for (int e = 0; e < 6; e++) acc[b][vi][e] = 0ULL;

    for (int j = 0; j < NJ; j++) {
        float4 w = *(const float4*)&d_wT[(size_t)j * NVP + v0];
        ull ws[4] = {splat2(w.x), splat2(w.y), splat2(w.z), splat2(w.w)};
#pragma unroll
        for (int b = 0; b < SK_BT; b++) {
            const ull* a2p = (const ull*)&A2_s[b][j * 12];
#pragma unroll
            for (int e = 0; e < 6; e++) {
                ull av = a2p[e];
                acc[b][0][e] = fma2(ws[0], av, acc[b][0][e]);
                acc[b][1][e] = fma2(ws[1], av, acc[b][1][e]);
                acc[b][2][e] = fma2(ws[2], av, acc[b][2][e]);
                acc[b][3][e] = fma2(ws[3], av, acc[b][3][e]);
            }
        }
    }

    bool full = (v0 + 3 < NV);
#pragma unroll
    for (int b = 0; b < SK_BT; b++) {
        int bglob = b0 + b;
        float tx = trans[bglob * 3 + 0], ty = trans[bglob * 3 + 1], tz = trans[bglob * 3 + 2];
        size_t base = (size_t)bglob * R3 + (size_t)v0 * 3;   // even -> float2-safe
        float o[12], nk[12];
        if (full) {
#pragma unroll
            for (int c = 0; c < 6; c++) {
                float2 t = *(const float2*)(naked_in + base + c * 2);
                nk[c * 2] = t.x; nk[c * 2 + 1] = t.y;
            }
        } else {
            int cnt = (NV - v0) * 3;
            for (int i = 0; i < 12; i++) nk[i] = (i < cnt) ? naked_in[base + i] : 0.f;
        }
#pragma unroll
        for (int vi = 0; vi < 4; vi++) {
            float nx = nk[vi * 3 + 0], ny = nk[vi * 3 + 1], nz = nk[vi * 3 + 2];
            float2 t01 = unpack2(acc[b][vi][0]);
            float2 t23 = unpack2(acc[b][vi][1]);
            float2 t45 = unpack2(acc[b][vi][2]);
            float2 t67 = unpack2(acc[b][vi][3]);
            float2 t89 = unpack2(acc[b][vi][4]);
            float2 tab = unpack2(acc[b][vi][5]);
            o[vi * 3 + 0] = t01.x * nx + t01.y * ny + t23.x * nz + t23.y + tx;
            o[vi * 3 + 1] = t45.x * nx + t45.y * ny + t67.x * nz + t67.y + ty;
            o[vi * 3 + 2] = t89.x * nx + t89.y * ny + tab.x * nz + tab.y + tz;
        }
        if (full) {
#pragma unroll
            for (int c = 0; c < 6; c++)
                *(float2*)(out_verts + base + c * 2) = make_float2(o[c * 2], o[c * 2 + 1]);
        } else {
            int cnt = (NV - v0) * 3;
            for (int i = 0; i < 12 && i < cnt; i++) out_verts[base + i] = o[i];
        }
    }
}

// ---------------------------------------------------------------------------
extern "C" void kernel_launch(void* const* d_in, const int* in_sizes, int n_in,
                              void* d_out, int out_size) {
    (void)in_sizes; (void)n_in; (void)out_size;
    const float* pose  = (const float*)d_in[0];
    const float* betas = (const float*)d_in[1];
    const float* trans = (const float*)d_in[2];
    const float* vt    = (const float*)d_in[3];
    const float* sd    = (const float*)d_in[4];
    const float* pd    = (const float*)d_in[5];
    const float* Jreg  = (const float*)d_in[6];
    const float* wgt   = (const float*)d_in[7];

    float* out        = (float*)d_out;
    float* out_verts  = out;
    float* out_jtr    = out_verts + (size_t)BATCH * R3;
    float* out_vposed = out_jtr   + (size_t)BATCH * NJ * 3;
    float* out_naked  = out_vposed + (size_t)BATCH * R3;

    void* p_wT;
    cudaGetSymbolAddress(&p_wT, d_wT);

    int convThreads = MROWS * 60;
    convertR_kernel<<<(convThreads + 255) / 256, 256>>>(pd, sd, vt);              // 0
    jreg_kernel<<<NJ, 256>>>(Jreg, vt, sd);                                       // 1
    pose_kernel<<<BATCH, 64>>>(pose, betas, trans, out_jtr);                      // 2
    mma_naked_kernel<<<dim3(162, 4), 256>>>(out_vposed, out_naked);               // 3
    dim3 tb(32, 8);
    transpose_kernel<<<dim3((NJ + 31) / 32, (NV + 31) / 32), tb>>>(wgt, (float*)p_wT, NV, NJ, NVP); // 4
    skin_kernel<<<dim3((NV / 4 + 127) / 128, BATCH / SK_BT), 128>>>(trans, out_naked, out_verts);   // 5
}